// round 16
// baseline (speedup 1.0000x reference)
#include <cuda_runtime.h>
#include <cuda_fp16.h>
#include <cstdint>

// ---------------------------------------------------------------------------
// NetVLAD GB300 round 15: R14 + restructured 3-term kC (W frags direct from
// gmem, 256 thr, split-fp16 V staging).  N=32, C=1024, D=128, K=64, S=784.
// ---------------------------------------------------------------------------

__device__ __align__(16) unsigned char g_wpk[589824];  // 16 chunks x 36864B W image
__device__ __align__(16) unsigned char g_wcpk[17408];  // Wconv fp16 [64 k][272B]
__device__ float g_vladraw[32 * 8192];
__device__ float g_vlad  [32 * 8192];
__device__ float g_sasum [32 * 64];
__device__ float g_proj  [32 * 1024];

__device__ __forceinline__ uint32_t smem_u32(const void* p) {
    uint32_t a;
    asm("{ .reg .u64 t; cvta.to.shared.u64 t, %1; cvt.u32.u64 %0, t; }"
        : "=r"(a) : "l"(p));
    return a;
}
__device__ __forceinline__ void cpasync16(uint32_t smem, const void* gmem) {
    asm volatile("cp.async.cg.shared.global [%0], [%1], 16;"
        :: "r"(smem), "l"(gmem) : "memory");
}
#define CP_COMMIT() asm volatile("cp.async.commit_group;" ::: "memory")
#define CP_WAIT1()  asm volatile("cp.async.wait_group 1;" ::: "memory")

__device__ __forceinline__ void ldsm(unsigned* r, uint32_t a) {
    asm volatile("ldmatrix.sync.aligned.m8n8.x4.shared.b16 {%0,%1,%2,%3}, [%4];"
        : "=r"(r[0]), "=r"(r[1]), "=r"(r[2]), "=r"(r[3]) : "r"(a));
}
__device__ __forceinline__ void ldsmt(unsigned* r, uint32_t a) {
    asm volatile("ldmatrix.sync.aligned.m8n8.x4.trans.shared.b16 {%0,%1,%2,%3}, [%4];"
        : "=r"(r[0]), "=r"(r[1]), "=r"(r[2]), "=r"(r[3]) : "r"(a));
}
__device__ __forceinline__ void mma_f16(float* c, const unsigned* a, const unsigned* b) {
    asm volatile(
        "mma.sync.aligned.m16n8k16.row.col.f32.f16.f16.f32 "
        "{%0,%1,%2,%3}, {%4,%5,%6,%7}, {%8,%9}, {%0,%1,%2,%3};"
        : "+f"(c[0]), "+f"(c[1]), "+f"(c[2]), "+f"(c[3])
        : "r"(a[0]), "r"(a[1]), "r"(a[2]), "r"(a[3]), "r"(b[0]), "r"(b[1]));
}

// ---------------------------------------------------------------------------
// kInit: zero accumulators + pack Wpool hi/lo image + Wconv fp16 image
// ---------------------------------------------------------------------------
__global__ void kInit(const float* __restrict__ Wpool,
                      const float* __restrict__ Wconv) {
    int idx = blockIdx.x * 256 + threadIdx.x;
    if (idx < 262144) g_vladraw[idx] = 0.f;
    if (idx < 2048)   g_sasum[idx] = 0.f;
    if (idx < 32768)  g_proj[idx] = 0.f;
    if (idx < 131072) {
        int d = idx >> 10, c = idx & 1023;
        float w = Wpool[idx];
        __half h = __float2half_rn(w);
        __half l = __float2half_rn(w - __half2float(h));
        int q = c >> 6, cl = c & 63;
        *(__half*)(g_wpk + q * 36864 + d * 144 + cl * 2) = h;
        *(__half*)(g_wpk + q * 36864 + 18432 + d * 144 + cl * 2) = l;
    }
    if (idx < 8192) {
        int k = idx >> 7, d = idx & 127;
        *(__half*)(g_wcpk + k * 272 + d * 2) = __float2half_rn(Wconv[idx]);
    }
}

// ---------------------------------------------------------------------------
// kA: fp16 2-term mma pool GEMM (128d x 64s) + fully-HMMA epilogue
// grid (13, 32), 256 thr, dyn smem 93184 B  (proven R11/R13/R14 version)
// ---------------------------------------------------------------------------
__global__ void __launch_bounds__(256, 2) kA(const float* __restrict__ x,
                                             const float* __restrict__ bpool,
                                             const float* __restrict__ bconv) {
    extern __shared__ char smc[];
    float* smf = (float*)smc;
    const uint32_t sb = smem_u32(smc);

    const int tid = threadIdx.x, lane = tid & 31, wid = tid >> 5;
    const int n = blockIdx.y;
    const int s0 = blockIdx.x * 64;
    const bool fullv = (blockIdx.x < 12);

    const float* xn = x + (size_t)n * 1024 * 784;
    const int xc = tid >> 2, xs = (tid & 3) * 16;

    const int wd = wid & 3, ws = wid >> 2;
    const int md0 = wd * 32, ns0 = ws * 32;
    const int mat = lane >> 3, rr = lane & 7;
    const uint32_t aH0 = sb + 1024 + (uint32_t)(md0 + ((mat & 1) << 3) + rr) * 144
                         + ((uint32_t)(mat >> 1) << 4);
    const uint32_t bH0 = sb + 1024 + 36864 + (uint32_t)(((mat & 1) << 3) + rr) * 144
                         + (uint32_t)(ns0 + ((mat >> 1) << 3)) * 2;

    float acc[2][4][4];
#pragma unroll
    for (int mt = 0; mt < 2; mt++)
#pragma unroll
        for (int nf = 0; nf < 4; nf++)
#pragma unroll
            for (int u = 0; u < 4; u++) acc[mt][nf][u] = 0.f;

    float xr[16];

#define LOADX(q) do { \
    const float* p0 = xn + (size_t)((q) * 64 + xc) * 784 + s0 + xs; \
    if (fullv) { \
        _Pragma("unroll") \
        for (int u = 0; u < 4; u++) { \
            float4 a4 = ((const float4*)p0)[u]; \
            xr[u * 4] = a4.x; xr[u * 4 + 1] = a4.y; \
            xr[u * 4 + 2] = a4.z; xr[u * 4 + 3] = a4.w; \
        } \
    } else { \
        _Pragma("unroll") \
        for (int i = 0; i < 16; i++) \
            xr[i] = ((s0 + xs + i) < 784) ? p0[i] : 0.f; \
    } } while (0)

#define STOREX(b) do { \
    char* xh = smc + 1024 + (b) * 46080 + 36864 + xc * 144 + xs * 2; \
    _Pragma("unroll") \
    for (int i = 0; i < 8; i++) { \
        __half2 hp = __floats2half2_rn(xr[2 * i], xr[2 * i + 1]); \
        *(uint32_t*)(xh + i * 4) = *(uint32_t*)&hp; \
    } } while (0)

#define COPYW(q, b) do { \
    const unsigned char* src = g_wpk + (q) * 36864; \
    uint32_t dst = sb + 1024 + (b) * 46080; \
    _Pragma("unroll") \
    for (int i = 0; i < 9; i++) { \
        int seg = tid + i * 256; \
        cpasync16(dst + seg * 16, src + seg * 16); \
    } } while (0)

    LOADX(0);
    COPYW(0, 0); CP_COMMIT();
    COPYW(1, 1); CP_COMMIT();

    for (int q = 0; q < 16; q++) {
        const int b = q & 1;
        STOREX(b);
        if (q + 1 < 16) LOADX(q + 1);
        CP_WAIT1();
        __syncthreads();

        const uint32_t aH = aH0 + b * 46080;
        const uint32_t aL = aH + 18432;
        const uint32_t bH = bH0 + b * 46080;
#pragma unroll
        for (int ks = 0; ks < 4; ks++) {
            unsigned ah[2][4], al[2][4];
            ldsm(ah[0], aH + ks * 32);
            ldsm(ah[1], aH + ks * 32 + 2304);
            ldsm(al[0], aL + ks * 32);
            ldsm(al[1], aL + ks * 32 + 2304);
            unsigned bh[2][4];
#pragma unroll
            for (int nt = 0; nt < 2; nt++)
                ldsmt(bh[nt], bH + ks * 2304 + nt * 32);
#pragma unroll
            for (int mt = 0; mt < 2; mt++)
#pragma unroll
                for (int nf = 0; nf < 4; nf++) {
                    const unsigned* bhf = &bh[nf >> 1][(nf & 1) * 2];
                    mma_f16(acc[mt][nf], ah[mt], bhf);
                    mma_f16(acc[mt][nf], al[mt], bhf);
                }
        }
        __syncthreads();
        if (q + 2 < 16) COPYW(q + 2, b);
        CP_COMMIT();
    }
#undef LOADX
#undef STOREX
#undef COPYW

    const int r0w = lane >> 2, cq = lane & 3;

    // ---- acc -> XF_A[d][68 s] fp32 (+bias) ----
    {
#pragma unroll
        for (int mt = 0; mt < 2; mt++) {
            int d = md0 + mt * 16 + r0w;
            float b0 = __ldg(&bpool[d]);
            float b8 = __ldg(&bpool[d + 8]);
#pragma unroll
            for (int nf = 0; nf < 4; nf++) {
                int s = ns0 + nf * 8 + cq * 2;
                smf[256 + d * 68 + s]           = acc[mt][nf][0] + b0;
                smf[256 + d * 68 + s + 1]       = acc[mt][nf][1] + b0;
                smf[256 + (d + 8) * 68 + s]     = acc[mt][nf][2] + b8;
                smf[256 + (d + 8) * 68 + s + 1] = acc[mt][nf][3] + b8;
            }
        }
    }
    __syncthreads();

    // ---- column L2 norm over d ----
    if (tid < 64) {
        float s = 0.f;
#pragma unroll 8
        for (int d = 0; d < 128; d++) {
            float v = smf[256 + d * 68 + tid];
            s += v * v;
        }
        smf[17920 + tid] = ((s0 + tid) < 784) ? 1.f / fmaxf(sqrtf(s), 1e-12f) : 0.f;
    }
    __syncthreads();

    // ---- build fp16 xf tiles: XF16_ds [d][144B] and XF16_sd [s][272B] ----
    {
        const int row = tid & 127, hs = tid >> 7;
#pragma unroll
        for (int g = 0; g < 8; g++) {
            int s4 = hs * 32 + g * 4;
            float4 v = *(const float4*)&smf[256 + row * 68 + s4];
            float4 m = *(const float4*)&smf[17920 + s4];
            v.x *= m.x; v.y *= m.y; v.z *= m.z; v.w *= m.w;
            __half2 h01 = __floats2half2_rn(v.x, v.y);
            __half2 h23 = __floats2half2_rn(v.z, v.w);
            *(uint32_t*)(smc + 35840 + row * 144 + s4 * 2)     = *(uint32_t*)&h01;
            *(uint32_t*)(smc + 35840 + row * 144 + s4 * 2 + 4) = *(uint32_t*)&h23;
            *(__half*)(smc + 54272 + (s4 + 0) * 272 + row * 2) = __low2half(h01);
            *(__half*)(smc + 54272 + (s4 + 1) * 272 + row * 2) = __high2half(h01);
            *(__half*)(smc + 54272 + (s4 + 2) * 272 + row * 2) = __low2half(h23);
            *(__half*)(smc + 54272 + (s4 + 3) * 272 + row * 2) = __high2half(h23);
        }
    }
    __syncthreads();

    // ---- copy Wconv fp16 image into regionA ----
    {
        const uint4* src = (const uint4*)g_wcpk;
        uint4* dst = (uint4*)(smc + 1024);
#pragma unroll
        for (int i = 0; i < 5; i++) {
            int seg = tid + i * 256;
            if (seg < 1088) dst[seg] = src[seg];
        }
    }
    __syncthreads();

    // ---- logits mma: M=64(k) N=64(s) K=128(d) ----
    float accl[4][4];
#pragma unroll
    for (int nf = 0; nf < 4; nf++)
#pragma unroll
        for (int u = 0; u < 4; u++) accl[nf][u] = 0.f;
    {
        const uint32_t aW = sb + 1024 + (uint32_t)(16 * wd + ((mat & 1) << 3) + rr) * 272
                            + ((uint32_t)(mat >> 1) << 4);
        const uint32_t bL = sb + 35840 + (uint32_t)(((mat & 1) << 3) + rr) * 144
                            + (uint32_t)(32 * ws + ((mat >> 1) << 3)) * 2;
#pragma unroll
        for (int ks = 0; ks < 8; ks++) {
            unsigned a[4];
            ldsm(a, aW + ks * 32);
            unsigned bb[2][4];
            ldsmt(bb[0], bL + ks * 2304);
            ldsmt(bb[1], bL + ks * 2304 + 32);
#pragma unroll
            for (int nf = 0; nf < 4; nf++)
                mma_f16(accl[nf], a, &bb[nf >> 1][(nf & 1) * 2]);
        }
    }
    __syncthreads();

    // ---- bias + store logits -> EP_log [s][68] fp32 @ float 256 ----
    {
        float bc0 = __ldg(&bconv[16 * wd + r0w]);
        float bc1 = __ldg(&bconv[16 * wd + r0w + 8]);
#pragma unroll
        for (int nf = 0; nf < 4; nf++) {
            int s = 32 * ws + nf * 8 + cq * 2;
            smf[256 + s * 68 + 16 * wd + r0w]           = accl[nf][0] + bc0;
            smf[256 + (s + 1) * 68 + 16 * wd + r0w]     = accl[nf][1] + bc0;
            smf[256 + s * 68 + 16 * wd + r0w + 8]       = accl[nf][2] + bc1;
            smf[256 + (s + 1) * 68 + 16 * wd + r0w + 8] = accl[nf][3] + bc1;
        }
    }
    __syncthreads();

    // ---- softmax over K=64 per s ----
    {
        const int sidx = tid & 63, kg = tid >> 6;
        float lv[16];
        float mx = -1e30f;
#pragma unroll
        for (int i = 0; i < 16; i++) {
            lv[i] = smf[256 + sidx * 68 + kg * 16 + i];
            mx = fmaxf(mx, lv[i]);
        }
        smf[17984 + sidx * 5 + kg] = mx;
        __syncthreads();
        float M = fmaxf(fmaxf(smf[17984 + sidx * 5], smf[17984 + sidx * 5 + 1]),
                        fmaxf(smf[17984 + sidx * 5 + 2], smf[17984 + sidx * 5 + 3]));
        float es = 0.f;
#pragma unroll
        for (int i = 0; i < 16; i++) { lv[i] = __expf(lv[i] - M); es += lv[i]; }
        smf[18304 + sidx * 5 + kg] = es;
        __syncthreads();
        float tot = smf[18304 + sidx * 5] + smf[18304 + sidx * 5 + 1]
                  + smf[18304 + sidx * 5 + 2] + smf[18304 + sidx * 5 + 3];
        float r = ((s0 + sidx) < 784) ? 1.f / tot : 0.f;
#pragma unroll
        for (int i = 0; i < 16; i++)
            *(__half*)(smc + 18432 + (kg * 16 + i) * 144 + sidx * 2) =
                __float2half_rn(lv[i] * r);
    }
    __syncthreads();

    // ---- sasum from rounded sa ----
    if (tid < 64) {
        const __half2* rp = (const __half2*)(smc + 18432 + tid * 144);
        float s = 0.f;
#pragma unroll
        for (int i = 0; i < 32; i++) {
            float2 f = __half22float2(rp[i]);
            s += f.x + f.y;
        }
        atomicAdd(&g_sasum[n * 64 + tid], s);
    }

    // ---- vlad mma: M=64(k) N=128(d) K=64(s) ----
    {
        const uint32_t aV = sb + 18432 + (uint32_t)(16 * wd + ((mat & 1) << 3) + rr) * 144
                            + ((uint32_t)(mat >> 1) << 4);
        const uint32_t bV = sb + 54272 + (uint32_t)(((mat & 1) << 3) + rr) * 272
                            + (uint32_t)(64 * ws + ((mat >> 1) << 3)) * 2;
        float accv[8][4];
#pragma unroll
        for (int nf = 0; nf < 8; nf++)
#pragma unroll
            for (int u = 0; u < 4; u++) accv[nf][u] = 0.f;
#pragma unroll
        for (int ks = 0; ks < 4; ks++) {
            unsigned a[4];
            ldsm(a, aV + ks * 32);
            unsigned bb[4][4];
#pragma unroll
            for (int nt = 0; nt < 4; nt++)
                ldsmt(bb[nt], bV + ks * 4352 + nt * 32);
#pragma unroll
            for (int nf = 0; nf < 8; nf++)
                mma_f16(accv[nf], a, &bb[nf >> 1][(nf & 1) * 2]);
        }
        float* vr = g_vladraw + (size_t)n * 8192;
        const int k0 = 16 * wd + r0w, k1 = k0 + 8;
#pragma unroll
        for (int nf = 0; nf < 8; nf++) {
            int d = 64 * ws + nf * 8 + cq * 2;
            atomicAdd(&vr[k0 * 128 + d],     accv[nf][0]);
            atomicAdd(&vr[k0 * 128 + d + 1], accv[nf][1]);
            atomicAdd(&vr[k1 * 128 + d],     accv[nf][2]);
            atomicAdd(&vr[k1 * 128 + d + 1], accv[nf][3]);
        }
    }
}

// ---------------------------------------------------------------------------
// kBfin: vlad = vladraw - centroids*sasum, intra-norm over K
// ---------------------------------------------------------------------------
__global__ void __launch_bounds__(256) kBfin(const float* __restrict__ centroids) {
    __shared__ float ssm[64];
    __shared__ float red[8][33];
    const int dt = blockIdx.x, n = blockIdx.y, tid = threadIdx.x;
    const int dl = tid & 31, kg = tid >> 5;
    const int d = dt * 32 + dl;
    if (tid < 64) ssm[tid] = g_sasum[n * 64 + tid];
    __syncthreads();
    const float* vr = g_vladraw + (size_t)n * 8192;
    float v[8], sq = 0.f;
#pragma unroll
    for (int j = 0; j < 8; j++) {
        int k = kg * 8 + j;
        float val = vr[k * 128 + d] - centroids[k * 128 + d] * ssm[k];
        v[j] = val;
        sq += val * val;
    }
    red[kg][dl] = sq;
    __syncthreads();
    float tot = 0.f;
#pragma unroll
    for (int t = 0; t < 8; t++) tot += red[t][dl];
    float inv = 1.f / fmaxf(sqrtf(tot), 1e-12f);
    float* vo = g_vlad + (size_t)n * 8192;
#pragma unroll
    for (int j = 0; j < 8; j++)
        vo[(kg * 8 + j) * 128 + d] = v[j] * inv;
}

// ---------------------------------------------------------------------------
// kC: proj = vlad @ Wproj^T, 3-term fp16 HMMA.
// grid (16 o-tiles of 64, 16 j-splits of 512), 256 thr (8 warps: 4 o x 2 j),
// dyn smem 40960 B: buf(b) @ b*20480: VH [128 j][40h=80B] | VL @ +10240
// W fragments loaded directly from gmem (float2 quads), split in registers.
// ---------------------------------------------------------------------------
__global__ void __launch_bounds__(256) kC(const float* __restrict__ Wproj) {
    extern __shared__ __align__(16) unsigned char smv[];
    const int tid = threadIdx.x, lane = tid & 31, w = tid >> 5;
    const int wo = w & 3, wj = w >> 2;
    const int ob = blockIdx.x * 64;
    const int jb = blockIdx.y * 512;
    const int mat = lane >> 3, rr = lane & 7;
    const uint32_t sb = smem_u32(smv);

    float acc[4][4];
#pragma unroll
    for (int nf = 0; nf < 4; nf++)
#pragma unroll
        for (int u = 0; u < 4; u++) acc[nf][u] = 0.f;

    // V staging: thread -> n pair (vn2, vn2+1), j group of 8
    const int vn2 = (tid & 15) * 2, vj8 = (tid >> 4) * 8;
    float vrg[16];

#define LOADV(c) do { \
    const float* p0 = g_vlad + (size_t)vn2 * 8192 + jb + (c) * 128 + vj8; \
    float4 a0 = ((const float4*)p0)[0], a1 = ((const float4*)p0)[1]; \
    const float* p1 = p0 + 8192; \
    float4 b0 = ((const float4*)p1)[0], b1 = ((const float4*)p1)[1]; \
    vrg[0] = a0.x; vrg[1] = a0.y; vrg[2] = a0.z; vrg[3] = a0.w; \
    vrg[4] = a1.x; vrg[5] = a1.y; vrg[6] = a1.z; vrg[7] = a1.w; \
    vrg[8] = b0.x; vrg[9] = b0.y; vrg[10] = b0.z; vrg[11] = b0.w; \
    vrg[12] = b1.x; vrg[13] = b1.y; vrg[14] = b1.z; vrg[15] = b1.w; \
    } while (0)

#define STOREV(b) do { \
    _Pragma("unroll") \
    for (int e = 0; e < 8; e++) { \
        int jl = vj8 + e; \
        float f0 = vrg[e], f1 = vrg[8 + e]; \
        __half h0 = __float2half_rn(f0), h1 = __float2half_rn(f1); \
        __half l0 = __float2half_rn(f0 - __half2float(h0)); \
        __half l1 = __float2half_rn(f1 - __half2float(h1)); \
        __half2 th; th.x = h0; th.y = h1; \
        __half2 tl; tl.x = l0; tl.y = l1; \
        *(uint32_t*)(smv + (b) * 20480 + jl * 80 + vn2 * 2) = *(uint32_t*)&th; \
        *(uint32_t*)(smv + (b) * 20480 + 10240 + jl * 80 + vn2 * 2) = *(uint32_t*)&tl; \
    } } while (0)

    // W fragment: rows r, r+8; cols c0..c0+1 and c0+8..+9 per 16-k step
    const float* Wbase = Wproj + (size_t)(ob + wo * 16 + (lane >> 2)) * 8192
                         + jb + wj * 64 + (lane & 3) * 2;
    float2 wr2[4];

#define LOADW(it) do { \
    const float* p = Wbase + ((it) >> 2) * 128 + ((it) & 3) * 16; \
    wr2[0] = *(const float2*)p; \
    wr2[1] = *(const float2*)(p + 8); \
    wr2[2] = *(const float2*)(p + 8 * 8192); \
    wr2[3] = *(const float2*)(p + 8 * 8192 + 8); \
    } while (0)

#define WSPLIT(i, j) do { \
    float f0 = wr2[j].x, f1 = wr2[j].y; \
    __half h0 = __float2half_rn(f0), h1 = __float2half_rn(f1); \
    __half l0 = __float2half_rn(f0 - __half2float(h0)); \
    __half l1 = __float2half_rn(f1 - __half2float(h1)); \
    __half2 th; th.x = h0; th.y = h1; ah[i] = *(uint32_t*)&th; \
    __half2 tl; tl.x = l0; tl.y = l1; al[i] = *(uint32_t*)&tl; \
    } while (0)

    const uint32_t bB0 = sb + (uint32_t)(wj * 64 + ((mat & 1) << 3) + rr) * 80
                         + ((uint32_t)(mat >> 1) << 4);

    LOADV(0); STOREV(0); LOADV(1);
    __syncthreads();
    LOADW(0);

    for (int c = 0; c < 4; c++) {
        const int b = c & 1;
        if (c + 1 < 4) STOREV((c + 1) & 1);
        if (c + 2 < 4) LOADV(c + 2);
#pragma unroll
        for (int ks = 0; ks < 4; ks++) {
            unsigned ah[4], al[4];
            WSPLIT(0, 0); WSPLIT(1, 2); WSPLIT(2, 1); WSPLIT(3, 3);
            int it = c * 4 + ks;
            if (it + 1 < 16) LOADW(it + 1);
            const uint32_t bH = bB0 + b * 20480 + ks * 1280;
            const uint32_t bL = bH + 10240;
            unsigned bh[2][4], bl[2][4];
            ldsmt(bh[0], bH);
            ldsmt(bh[1], bH + 32);
            ldsmt(bl[0], bL);
            ldsmt(bl[1], bL + 32);
#pragma unroll
            for (int nf = 0; nf < 4; nf++) {
                const unsigned* bhf = &bh[nf >> 1][(nf & 1) * 2];
                const unsigned* blf = &bl[nf >> 1][(nf & 1) * 2];
                mma_f16(acc[nf], ah, bhf);
                mma_f16(acc[nf], al, bhf);
                mma_f16(acc[nf], ah, blf);
            }
        }
        __syncthreads();
    }
#undef LOADV
#undef STOREV
#undef LOADW
#undef WSPLIT

    // C fragment: row = o (lane>>2 [+8]), col = n (nf*8 + (lane&3)*2 [+1])
    {
        const int o0 = ob + wo * 16 + (lane >> 2);
        const int o1 = o0 + 8;
#pragma unroll
        for (int nf = 0; nf < 4; nf++) {
            int n0 = nf * 8 + (lane & 3) * 2;
            atomicAdd(&g_proj[(n0 + 0) * 1024 + o0], acc[nf][0]);
            atomicAdd(&g_proj[(n0 + 1) * 1024 + o0], acc[nf][1]);
            atomicAdd(&g_proj[(n0 + 0) * 1024 + o1], acc[nf][2]);
            atomicAdd(&g_proj[(n0 + 1) * 1024 + o1], acc[nf][3]);
        }
    }
}

// ---------------------------------------------------------------------------
__global__ void __launch_bounds__(256) kD(const float* __restrict__ bproj,
                                          float* __restrict__ out) {
    __shared__ float wr[8];
    __shared__ float inv_s;
    const int n = blockIdx.x, tid = threadIdx.x;
    float v[4]; float ps = 0.f;
#pragma unroll
    for (int r = 0; r < 4; r++) {
        int o = r * 256 + tid;
        v[r] = g_proj[n * 1024 + o] + bproj[o];
        ps += v[r] * v[r];
    }
#pragma unroll
    for (int off = 16; off; off >>= 1)
        ps += __shfl_xor_sync(0xffffffffu, ps, off);
    if ((tid & 31) == 0) wr[tid >> 5] = ps;
    __syncthreads();
    if (tid == 0) {
        float s = 0.f;
#pragma unroll
        for (int t = 0; t < 8; t++) s += wr[t];
        inv_s = 1.f / fmaxf(sqrtf(s), 1e-12f);
    }
    __syncthreads();
#pragma unroll
    for (int r = 0; r < 4; r++)
        out[n * 1024 + r * 256 + tid] = v[r] * inv_s;
}

// ---------------------------------------------------------------------------
extern "C" void kernel_launch(void* const* d_in, const int* in_sizes, int n_in,
                              void* d_out, int out_size) {
    const float* x         = (const float*)d_in[0];
    const float* Wpool     = (const float*)d_in[1];
    const float* bpool     = (const float*)d_in[2];
    const float* Wconv     = (const float*)d_in[3];
    const float* bconv     = (const float*)d_in[4];
    const float* centroids = (const float*)d_in[5];
    const float* Wproj     = (const float*)d_in[6];
    const float* bproj     = (const float*)d_in[7];
    float* out = (float*)d_out;

    cudaFuncSetAttribute(kA, cudaFuncAttributeMaxDynamicSharedMemorySize, 93184);
    cudaFuncSetAttribute(kC, cudaFuncAttributeMaxDynamicSharedMemorySize, 40960);

    kInit<<<1024, 256>>>(Wpool, Wconv);
    dim3 gA(13, 32);
    kA<<<gA, 256, 93184>>>(x, bpool, bconv);
    dim3 gB(4, 32);
    kBfin<<<gB, 256>>>(centroids);
    dim3 gC(16, 16);
    kC<<<gC, 256, 40960>>>(Wproj);
    kD<<<32, 256>>>(bproj, out);
}

// round 17
// speedup vs baseline: 1.5271x; 1.5271x over previous
#include <cuda_runtime.h>
#include <cuda_fp16.h>
#include <cstdint>

// ---------------------------------------------------------------------------
// NetVLAD GB300 round 16: R14 base + split-fp16 vlad image (g_vpk) feeding a
// cp.async/ldsm/mma kC.  N=32, C=1024, D=128, K=64, S=784, OUT=1024
// ---------------------------------------------------------------------------

__device__ __align__(16) unsigned char g_wpk[589824];   // Wpool hi/lo chunk images
__device__ __align__(16) unsigned char g_wcpk[17408];   // Wconv fp16 [64 k][272B]
__device__ __align__(16) unsigned char g_vpk[1310720];  // vlad split: 128 ch x (VH 5120|VL 5120)
__device__ float g_vladraw[32 * 8192];
__device__ float g_sasum [32 * 64];
__device__ float g_proj  [32 * 1024];

__device__ __forceinline__ uint32_t smem_u32(const void* p) {
    uint32_t a;
    asm("{ .reg .u64 t; cvta.to.shared.u64 t, %1; cvt.u32.u64 %0, t; }"
        : "=r"(a) : "l"(p));
    return a;
}
__device__ __forceinline__ void cpasync16(uint32_t smem, const void* gmem) {
    asm volatile("cp.async.cg.shared.global [%0], [%1], 16;"
        :: "r"(smem), "l"(gmem) : "memory");
}
#define CP_COMMIT() asm volatile("cp.async.commit_group;" ::: "memory")
#define CP_WAIT1()  asm volatile("cp.async.wait_group 1;" ::: "memory")

__device__ __forceinline__ void ldsm(unsigned* r, uint32_t a) {
    asm volatile("ldmatrix.sync.aligned.m8n8.x4.shared.b16 {%0,%1,%2,%3}, [%4];"
        : "=r"(r[0]), "=r"(r[1]), "=r"(r[2]), "=r"(r[3]) : "r"(a));
}
__device__ __forceinline__ void ldsmt(unsigned* r, uint32_t a) {
    asm volatile("ldmatrix.sync.aligned.m8n8.x4.trans.shared.b16 {%0,%1,%2,%3}, [%4];"
        : "=r"(r[0]), "=r"(r[1]), "=r"(r[2]), "=r"(r[3]) : "r"(a));
}
__device__ __forceinline__ void mma_f16(float* c, const unsigned* a, const unsigned* b) {
    asm volatile(
        "mma.sync.aligned.m16n8k16.row.col.f32.f16.f16.f32 "
        "{%0,%1,%2,%3}, {%4,%5,%6,%7}, {%8,%9}, {%0,%1,%2,%3};"
        : "+f"(c[0]), "+f"(c[1]), "+f"(c[2]), "+f"(c[3])
        : "r"(a[0]), "r"(a[1]), "r"(a[2]), "r"(a[3]), "r"(b[0]), "r"(b[1]));
}

// ---------------------------------------------------------------------------
// kInit: zero accumulators + pack Wpool hi/lo image + Wconv fp16 image
// ---------------------------------------------------------------------------
__global__ void kInit(const float* __restrict__ Wpool,
                      const float* __restrict__ Wconv) {
    int idx = blockIdx.x * 256 + threadIdx.x;
    if (idx < 262144) g_vladraw[idx] = 0.f;
    if (idx < 2048)   g_sasum[idx] = 0.f;
    if (idx < 32768)  g_proj[idx] = 0.f;
    if (idx < 131072) {
        int d = idx >> 10, c = idx & 1023;
        float w = Wpool[idx];
        __half h = __float2half_rn(w);
        __half l = __float2half_rn(w - __half2float(h));
        int q = c >> 6, cl = c & 63;
        *(__half*)(g_wpk + q * 36864 + d * 144 + cl * 2) = h;
        *(__half*)(g_wpk + q * 36864 + 18432 + d * 144 + cl * 2) = l;
    }
    if (idx < 8192) {
        int k = idx >> 7, d = idx & 127;
        *(__half*)(g_wcpk + k * 272 + d * 2) = __float2half_rn(Wconv[idx]);
    }
}

// ---------------------------------------------------------------------------
// kA: fp16 2-term mma pool GEMM (128d x 64s) + fully-HMMA epilogue
// grid (13, 32), 256 thr, dyn smem 93184 B  (proven R11/R13/R14 version)
// ---------------------------------------------------------------------------
__global__ void __launch_bounds__(256, 2) kA(const float* __restrict__ x,
                                             const float* __restrict__ bpool,
                                             const float* __restrict__ bconv) {
    extern __shared__ char smc[];
    float* smf = (float*)smc;
    const uint32_t sb = smem_u32(smc);

    const int tid = threadIdx.x, lane = tid & 31, wid = tid >> 5;
    const int n = blockIdx.y;
    const int s0 = blockIdx.x * 64;
    const bool fullv = (blockIdx.x < 12);

    const float* xn = x + (size_t)n * 1024 * 784;
    const int xc = tid >> 2, xs = (tid & 3) * 16;

    const int wd = wid & 3, ws = wid >> 2;
    const int md0 = wd * 32, ns0 = ws * 32;
    const int mat = lane >> 3, rr = lane & 7;
    const uint32_t aH0 = sb + 1024 + (uint32_t)(md0 + ((mat & 1) << 3) + rr) * 144
                         + ((uint32_t)(mat >> 1) << 4);
    const uint32_t bH0 = sb + 1024 + 36864 + (uint32_t)(((mat & 1) << 3) + rr) * 144
                         + (uint32_t)(ns0 + ((mat >> 1) << 3)) * 2;

    float acc[2][4][4];
#pragma unroll
    for (int mt = 0; mt < 2; mt++)
#pragma unroll
        for (int nf = 0; nf < 4; nf++)
#pragma unroll
            for (int u = 0; u < 4; u++) acc[mt][nf][u] = 0.f;

    float xr[16];

#define LOADX(q) do { \
    const float* p0 = xn + (size_t)((q) * 64 + xc) * 784 + s0 + xs; \
    if (fullv) { \
        _Pragma("unroll") \
        for (int u = 0; u < 4; u++) { \
            float4 a4 = ((const float4*)p0)[u]; \
            xr[u * 4] = a4.x; xr[u * 4 + 1] = a4.y; \
            xr[u * 4 + 2] = a4.z; xr[u * 4 + 3] = a4.w; \
        } \
    } else { \
        _Pragma("unroll") \
        for (int i = 0; i < 16; i++) \
            xr[i] = ((s0 + xs + i) < 784) ? p0[i] : 0.f; \
    } } while (0)

#define STOREX(b) do { \
    char* xh = smc + 1024 + (b) * 46080 + 36864 + xc * 144 + xs * 2; \
    _Pragma("unroll") \
    for (int i = 0; i < 8; i++) { \
        __half2 hp = __floats2half2_rn(xr[2 * i], xr[2 * i + 1]); \
        *(uint32_t*)(xh + i * 4) = *(uint32_t*)&hp; \
    } } while (0)

#define COPYW(q, b) do { \
    const unsigned char* src = g_wpk + (q) * 36864; \
    uint32_t dst = sb + 1024 + (b) * 46080; \
    _Pragma("unroll") \
    for (int i = 0; i < 9; i++) { \
        int seg = tid + i * 256; \
        cpasync16(dst + seg * 16, src + seg * 16); \
    } } while (0)

    LOADX(0);
    COPYW(0, 0); CP_COMMIT();
    COPYW(1, 1); CP_COMMIT();

    for (int q = 0; q < 16; q++) {
        const int b = q & 1;
        STOREX(b);
        if (q + 1 < 16) LOADX(q + 1);
        CP_WAIT1();
        __syncthreads();

        const uint32_t aH = aH0 + b * 46080;
        const uint32_t aL = aH + 18432;
        const uint32_t bH = bH0 + b * 46080;
#pragma unroll
        for (int ks = 0; ks < 4; ks++) {
            unsigned ah[2][4], al[2][4];
            ldsm(ah[0], aH + ks * 32);
            ldsm(ah[1], aH + ks * 32 + 2304);
            ldsm(al[0], aL + ks * 32);
            ldsm(al[1], aL + ks * 32 + 2304);
            unsigned bh[2][4];
#pragma unroll
            for (int nt = 0; nt < 2; nt++)
                ldsmt(bh[nt], bH + ks * 2304 + nt * 32);
#pragma unroll
            for (int mt = 0; mt < 2; mt++)
#pragma unroll
                for (int nf = 0; nf < 4; nf++) {
                    const unsigned* bhf = &bh[nf >> 1][(nf & 1) * 2];
                    mma_f16(acc[mt][nf], ah[mt], bhf);
                    mma_f16(acc[mt][nf], al[mt], bhf);
                }
        }
        __syncthreads();
        if (q + 2 < 16) COPYW(q + 2, b);
        CP_COMMIT();
    }
#undef LOADX
#undef STOREX
#undef COPYW

    const int r0w = lane >> 2, cq = lane & 3;

    // ---- acc -> XF_A[d][68 s] fp32 (+bias) ----
    {
#pragma unroll
        for (int mt = 0; mt < 2; mt++) {
            int d = md0 + mt * 16 + r0w;
            float b0 = __ldg(&bpool[d]);
            float b8 = __ldg(&bpool[d + 8]);
#pragma unroll
            for (int nf = 0; nf < 4; nf++) {
                int s = ns0 + nf * 8 + cq * 2;
                smf[256 + d * 68 + s]           = acc[mt][nf][0] + b0;
                smf[256 + d * 68 + s + 1]       = acc[mt][nf][1] + b0;
                smf[256 + (d + 8) * 68 + s]     = acc[mt][nf][2] + b8;
                smf[256 + (d + 8) * 68 + s + 1] = acc[mt][nf][3] + b8;
            }
        }
    }
    __syncthreads();

    // ---- column L2 norm over d ----
    if (tid < 64) {
        float s = 0.f;
#pragma unroll 8
        for (int d = 0; d < 128; d++) {
            float v = smf[256 + d * 68 + tid];
            s += v * v;
        }
        smf[17920 + tid] = ((s0 + tid) < 784) ? 1.f / fmaxf(sqrtf(s), 1e-12f) : 0.f;
    }
    __syncthreads();

    // ---- build fp16 xf tiles: XF16_ds [d][144B] and XF16_sd [s][272B] ----
    {
        const int row = tid & 127, hs = tid >> 7;
#pragma unroll
        for (int g = 0; g < 8; g++) {
            int s4 = hs * 32 + g * 4;
            float4 v = *(const float4*)&smf[256 + row * 68 + s4];
            float4 m = *(const float4*)&smf[17920 + s4];
            v.x *= m.x; v.y *= m.y; v.z *= m.z; v.w *= m.w;
            __half2 h01 = __floats2half2_rn(v.x, v.y);
            __half2 h23 = __floats2half2_rn(v.z, v.w);
            *(uint32_t*)(smc + 35840 + row * 144 + s4 * 2)     = *(uint32_t*)&h01;
            *(uint32_t*)(smc + 35840 + row * 144 + s4 * 2 + 4) = *(uint32_t*)&h23;
            *(__half*)(smc + 54272 + (s4 + 0) * 272 + row * 2) = __low2half(h01);
            *(__half*)(smc + 54272 + (s4 + 1) * 272 + row * 2) = __high2half(h01);
            *(__half*)(smc + 54272 + (s4 + 2) * 272 + row * 2) = __low2half(h23);
            *(__half*)(smc + 54272 + (s4 + 3) * 272 + row * 2) = __high2half(h23);
        }
    }
    __syncthreads();

    // ---- copy Wconv fp16 image into regionA ----
    {
        const uint4* src = (const uint4*)g_wcpk;
        uint4* dst = (uint4*)(smc + 1024);
#pragma unroll
        for (int i = 0; i < 5; i++) {
            int seg = tid + i * 256;
            if (seg < 1088) dst[seg] = src[seg];
        }
    }
    __syncthreads();

    // ---- logits mma: M=64(k) N=64(s) K=128(d) ----
    float accl[4][4];
#pragma unroll
    for (int nf = 0; nf < 4; nf++)
#pragma unroll
        for (int u = 0; u < 4; u++) accl[nf][u] = 0.f;
    {
        const uint32_t aW = sb + 1024 + (uint32_t)(16 * wd + ((mat & 1) << 3) + rr) * 272
                            + ((uint32_t)(mat >> 1) << 4);
        const uint32_t bL = sb + 35840 + (uint32_t)(((mat & 1) << 3) + rr) * 144
                            + (uint32_t)(32 * ws + ((mat >> 1) << 3)) * 2;
#pragma unroll
        for (int ks = 0; ks < 8; ks++) {
            unsigned a[4];
            ldsm(a, aW + ks * 32);
            unsigned bb[2][4];
            ldsmt(bb[0], bL + ks * 2304);
            ldsmt(bb[1], bL + ks * 2304 + 32);
#pragma unroll
            for (int nf = 0; nf < 4; nf++)
                mma_f16(accl[nf], a, &bb[nf >> 1][(nf & 1) * 2]);
        }
    }
    __syncthreads();

    // ---- bias + store logits -> EP_log [s][68] fp32 @ float 256 ----
    {
        float bc0 = __ldg(&bconv[16 * wd + r0w]);
        float bc1 = __ldg(&bconv[16 * wd + r0w + 8]);
#pragma unroll
        for (int nf = 0; nf < 4; nf++) {
            int s = 32 * ws + nf * 8 + cq * 2;
            smf[256 + s * 68 + 16 * wd + r0w]           = accl[nf][0] + bc0;
            smf[256 + (s + 1) * 68 + 16 * wd + r0w]     = accl[nf][1] + bc0;
            smf[256 + s * 68 + 16 * wd + r0w + 8]       = accl[nf][2] + bc1;
            smf[256 + (s + 1) * 68 + 16 * wd + r0w + 8] = accl[nf][3] + bc1;
        }
    }
    __syncthreads();

    // ---- softmax over K=64 per s ----
    {
        const int sidx = tid & 63, kg = tid >> 6;
        float lv[16];
        float mx = -1e30f;
#pragma unroll
        for (int i = 0; i < 16; i++) {
            lv[i] = smf[256 + sidx * 68 + kg * 16 + i];
            mx = fmaxf(mx, lv[i]);
        }
        smf[17984 + sidx * 5 + kg] = mx;
        __syncthreads();
        float M = fmaxf(fmaxf(smf[17984 + sidx * 5], smf[17984 + sidx * 5 + 1]),
                        fmaxf(smf[17984 + sidx * 5 + 2], smf[17984 + sidx * 5 + 3]));
        float es = 0.f;
#pragma unroll
        for (int i = 0; i < 16; i++) { lv[i] = __expf(lv[i] - M); es += lv[i]; }
        smf[18304 + sidx * 5 + kg] = es;
        __syncthreads();
        float tot = smf[18304 + sidx * 5] + smf[18304 + sidx * 5 + 1]
                  + smf[18304 + sidx * 5 + 2] + smf[18304 + sidx * 5 + 3];
        float r = ((s0 + sidx) < 784) ? 1.f / tot : 0.f;
#pragma unroll
        for (int i = 0; i < 16; i++)
            *(__half*)(smc + 18432 + (kg * 16 + i) * 144 + sidx * 2) =
                __float2half_rn(lv[i] * r);
    }
    __syncthreads();

    // ---- sasum from rounded sa ----
    if (tid < 64) {
        const __half2* rp = (const __half2*)(smc + 18432 + tid * 144);
        float s = 0.f;
#pragma unroll
        for (int i = 0; i < 32; i++) {
            float2 f = __half22float2(rp[i]);
            s += f.x + f.y;
        }
        atomicAdd(&g_sasum[n * 64 + tid], s);
    }

    // ---- vlad mma: M=64(k) N=128(d) K=64(s) ----
    {
        const uint32_t aV = sb + 18432 + (uint32_t)(16 * wd + ((mat & 1) << 3) + rr) * 144
                            + ((uint32_t)(mat >> 1) << 4);
        const uint32_t bV = sb + 54272 + (uint32_t)(((mat & 1) << 3) + rr) * 272
                            + (uint32_t)(64 * ws + ((mat >> 1) << 3)) * 2;
        float accv[8][4];
#pragma unroll
        for (int nf = 0; nf < 8; nf++)
#pragma unroll
            for (int u = 0; u < 4; u++) accv[nf][u] = 0.f;
#pragma unroll
        for (int ks = 0; ks < 4; ks++) {
            unsigned a[4];
            ldsm(a, aV + ks * 32);
            unsigned bb[4][4];
#pragma unroll
            for (int nt = 0; nt < 4; nt++)
                ldsmt(bb[nt], bV + ks * 4352 + nt * 32);
#pragma unroll
            for (int nf = 0; nf < 8; nf++)
                mma_f16(accv[nf], a, &bb[nf >> 1][(nf & 1) * 2]);
        }
        float* vr = g_vladraw + (size_t)n * 8192;
        const int k0 = 16 * wd + r0w, k1 = k0 + 8;
#pragma unroll
        for (int nf = 0; nf < 8; nf++) {
            int d = 64 * ws + nf * 8 + cq * 2;
            atomicAdd(&vr[k0 * 128 + d],     accv[nf][0]);
            atomicAdd(&vr[k0 * 128 + d + 1], accv[nf][1]);
            atomicAdd(&vr[k1 * 128 + d],     accv[nf][2]);
            atomicAdd(&vr[k1 * 128 + d + 1], accv[nf][3]);
        }
    }
}

// ---------------------------------------------------------------------------
// kBfin: vlad = vladraw - centroids*sasum, intra-norm over K, write split-fp16
// V image g_vpk (chunk jc = j>>6: VH [64 j][40h=80B] | VL @ +5120)
// grid (4 d-tiles, 32 n), 256 thr
// ---------------------------------------------------------------------------
__global__ void __launch_bounds__(256) kBfin(const float* __restrict__ centroids) {
    __shared__ float ssm[64];
    __shared__ float red[8][33];
    const int dt = blockIdx.x, n = blockIdx.y, tid = threadIdx.x;
    const int dl = tid & 31, kg = tid >> 5;
    const int d = dt * 32 + dl;
    if (tid < 64) ssm[tid] = g_sasum[n * 64 + tid];
    __syncthreads();
    const float* vr = g_vladraw + (size_t)n * 8192;
    float v[8], sq = 0.f;
#pragma unroll
    for (int j = 0; j < 8; j++) {
        int k = kg * 8 + j;
        float val = vr[k * 128 + d] - centroids[k * 128 + d] * ssm[k];
        v[j] = val;
        sq += val * val;
    }
    red[kg][dl] = sq;
    __syncthreads();
    float tot = 0.f;
#pragma unroll
    for (int t = 0; t < 8; t++) tot += red[t][dl];
    float inv = 1.f / fmaxf(sqrtf(tot), 1e-12f);
    const int jr = d & 63, dhi = d >> 6;
#pragma unroll
    for (int j = 0; j < 8; j++) {
        int k = kg * 8 + j;
        float val = v[j] * inv;
        __half h = __float2half_rn(val);
        __half l = __float2half_rn(val - __half2float(h));
        size_t cb = (size_t)(k * 2 + dhi) * 10240;
        *(__half*)(g_vpk + cb + jr * 80 + n * 2) = h;
        *(__half*)(g_vpk + cb + 5120 + jr * 80 + n * 2) = l;
    }
}

// ---------------------------------------------------------------------------
// kC: proj = vlad @ Wproj^T, 3-term fp16 HMMA.
// grid (16 o-tiles of 64, 16 j-splits of 512), 256 thr (8 warps: 4 o x 2 j),
// dyn smem 55296 B: buf(b) @ b*27648: Wf32 [64 o][68f=272B] 17408 | Vsplit 10240
// W fragments: LDS fp32 -> register split.  V: pre-split image via cp.async.
// ---------------------------------------------------------------------------
__global__ void __launch_bounds__(256, 3) kC(const float* __restrict__ Wproj) {
    extern __shared__ __align__(16) unsigned char smv[];
    const int tid = threadIdx.x, lane = tid & 31, w = tid >> 5;
    const int wo = w & 3, wj = w >> 2;
    const int ob = blockIdx.x * 64;
    const int jb = blockIdx.y * 512;
    const int mat = lane >> 3, rr = lane & 7;
    const uint32_t sb = smem_u32(smv);

    float acc[4][4];
#pragma unroll
    for (int nf = 0; nf < 4; nf++)
#pragma unroll
        for (int u = 0; u < 4; u++) acc[nf][u] = 0.f;

#define COPYWV(c, b) do { \
    uint32_t wdst = sb + (b) * 27648; \
    const float* wsrc = Wproj + (size_t)ob * 8192 + jb + (c) * 64; \
    _Pragma("unroll") \
    for (int i = 0; i < 4; i++) { \
        int seg = tid + i * 256; \
        int row = seg >> 4, cs = seg & 15; \
        cpasync16(wdst + row * 272 + cs * 16, wsrc + (size_t)row * 8192 + cs * 4); \
    } \
    uint32_t vdst = sb + (b) * 27648 + 17408; \
    const unsigned char* vsrc = g_vpk + ((size_t)(blockIdx.y * 8 + (c))) * 10240; \
    _Pragma("unroll") \
    for (int i = 0; i < 3; i++) { \
        int seg = tid + i * 256; \
        if (seg < 640) cpasync16(vdst + seg * 16, vsrc + seg * 16); \
    } } while (0)

#define SPLITP(hi2, lo2, f0, f1) do { \
    __half h0 = __float2half_rn(f0), h1 = __float2half_rn(f1); \
    __half l0 = __float2half_rn((f0) - __half2float(h0)); \
    __half l1 = __float2half_rn((f1) - __half2float(h1)); \
    __half2 th; th.x = h0; th.y = h1; hi2 = *(uint32_t*)&th; \
    __half2 tl; tl.x = l0; tl.y = l1; lo2 = *(uint32_t*)&tl; \
    } while (0)

    COPYWV(0, 0); CP_COMMIT();
    COPYWV(1, 1); CP_COMMIT();

    const int ar = wo * 16 + (lane >> 2);       // A row (o local)
    const int ac0 = wj * 32 + (lane & 3) * 2;   // A col base (j local)

    for (int c = 0; c < 8; c++) {
        const int b = c & 1;
        CP_WAIT1();
        __syncthreads();
        const float* wt = (const float*)(smv + b * 27648);
        const uint32_t vb = sb + b * 27648 + 17408;
#pragma unroll
        for (int ks = 0; ks < 2; ks++) {
            unsigned ah[4], al[4];
            {
                int cc = ac0 + ks * 16;
                float2 f00 = *(const float2*)&wt[ar * 68 + cc];
                float2 f10 = *(const float2*)&wt[(ar + 8) * 68 + cc];
                float2 f01 = *(const float2*)&wt[ar * 68 + cc + 8];
                float2 f11 = *(const float2*)&wt[(ar + 8) * 68 + cc + 8];
                SPLITP(ah[0], al[0], f00.x, f00.y);
                SPLITP(ah[1], al[1], f10.x, f10.y);
                SPLITP(ah[2], al[2], f01.x, f01.y);
                SPLITP(ah[3], al[3], f11.x, f11.y);
            }
            const uint32_t bH = vb + (uint32_t)(wj * 32 + ks * 16 + ((mat & 1) << 3) + rr) * 80
                                + ((uint32_t)(mat >> 1) << 4);
            unsigned bh[2][4], bl[2][4];
            ldsmt(bh[0], bH);
            ldsmt(bh[1], bH + 32);
            ldsmt(bl[0], bH + 5120);
            ldsmt(bl[1], bH + 5120 + 32);
#pragma unroll
            for (int nf = 0; nf < 4; nf++) {
                const unsigned* bhf = &bh[nf >> 1][(nf & 1) * 2];
                const unsigned* blf = &bl[nf >> 1][(nf & 1) * 2];
                mma_f16(acc[nf], ah, bhf);
                mma_f16(acc[nf], al, bhf);
                mma_f16(acc[nf], ah, blf);
            }
        }
        __syncthreads();
        if (c + 2 < 8) COPYWV(c + 2, b);
        CP_COMMIT();
    }
#undef COPYWV
#undef SPLITP

    // C fragment: row = o (lane>>2 [+8]), col = n (nf*8 + (lane&3)*2 [+1])
    {
        const int o0 = ob + wo * 16 + (lane >> 2);
        const int o1 = o0 + 8;
#pragma unroll
        for (int nf = 0; nf < 4; nf++) {
            int n0 = nf * 8 + (lane & 3) * 2;
            atomicAdd(&g_proj[(n0 + 0) * 1024 + o0], acc[nf][0]);
            atomicAdd(&g_proj[(n0 + 1) * 1024 + o0], acc[nf][1]);
            atomicAdd(&g_proj[(n0 + 0) * 1024 + o1], acc[nf][2]);
            atomicAdd(&g_proj[(n0 + 1) * 1024 + o1], acc[nf][3]);
        }
    }
}

// ---------------------------------------------------------------------------
__global__ void __launch_bounds__(256) kD(const float* __restrict__ bproj,
                                          float* __restrict__ out) {
    __shared__ float wr[8];
    __shared__ float inv_s;
    const int n = blockIdx.x, tid = threadIdx.x;
    float v[4]; float ps = 0.f;
#pragma unroll
    for (int r = 0; r < 4; r++) {
        int o = r * 256 + tid;
        v[r] = g_proj[n * 1024 + o] + bproj[o];
        ps += v[r] * v[r];
    }
#pragma unroll
    for (int off = 16; off; off >>= 1)
        ps += __shfl_xor_sync(0xffffffffu, ps, off);
    if ((tid & 31) == 0) wr[tid >> 5] = ps;
    __syncthreads();
    if (tid == 0) {
        float s = 0.f;
#pragma unroll
        for (int t = 0; t < 8; t++) s += wr[t];
        inv_s = 1.f / fmaxf(sqrtf(s), 1e-12f);
    }
    __syncthreads();
#pragma unroll
    for (int r = 0; r < 4; r++)
        out[n * 1024 + r * 256 + tid] = v[r] * inv_s;
}

// ---------------------------------------------------------------------------
extern "C" void kernel_launch(void* const* d_in, const int* in_sizes, int n_in,
                              void* d_out, int out_size) {
    const float* x         = (const float*)d_in[0];
    const float* Wpool     = (const float*)d_in[1];
    const float* bpool     = (const float*)d_in[2];
    const float* Wconv     = (const float*)d_in[3];
    const float* bconv     = (const float*)d_in[4];
    const float* centroids = (const float*)d_in[5];
    const float* Wproj     = (const float*)d_in[6];
    const float* bproj     = (const float*)d_in[7];
    float* out = (float*)d_out;

    cudaFuncSetAttribute(kA, cudaFuncAttributeMaxDynamicSharedMemorySize, 93184);
    cudaFuncSetAttribute(kC, cudaFuncAttributeMaxDynamicSharedMemorySize, 55296);

    kInit<<<1024, 256>>>(Wpool, Wconv);
    dim3 gA(13, 32);
    kA<<<gA, 256, 93184>>>(x, bpool, bconv);
    dim3 gB(4, 32);
    kBfin<<<gB, 256>>>(centroids);
    dim3 gC(16, 16);
    kC<<<gC, 256, 55296>>>(Wproj);
    kD<<<32, 256>>>(bproj, out);
}